// round 13
// baseline (speedup 1.0000x reference)
#include <cuda_runtime.h>
#include <cuda_bf16.h>
#include <cstdint>
#include <math.h>

// N = 131072 (rows), D = 512, K = 256 -- fixed by dataset
#define TEMP 10.0f

// ---------------------------------------------------------------------------
// Fragment-packed prototype operands, uint4-pair order (two n-tiles per 16B):
// gB1: [c 16][s 2][tp 16][lane 32] uint4   (t = 2*tp + half; r in low/high)
// gB2: [half 2][c 8][s 2][tp 16][lane 32] uint4
// 256 KB per split each; L2-resident for the whole kernel (read by all CTAs).
// ---------------------------------------------------------------------------
__device__ __align__(16) unsigned char g_b1h[262144];
__device__ __align__(16) unsigned char g_b1l[262144];
__device__ __align__(16) unsigned char g_b2h[262144];
__device__ __align__(16) unsigned char g_b2l[262144];

__device__ __forceinline__ void split2(float x, float y, uint32_t& hi, uint32_t& lo) {
    __nv_bfloat16 hx = __float2bfloat16(x), hy = __float2bfloat16(y);
    float rx = x - __bfloat162float(hx);
    float ry = y - __bfloat162float(hy);
    __nv_bfloat16 lx = __float2bfloat16(rx), ly = __float2bfloat16(ry);
    hi = ((uint32_t)__bfloat16_as_ushort(hy) << 16) | __bfloat16_as_ushort(hx);
    lo = ((uint32_t)__bfloat16_as_ushort(ly) << 16) | __bfloat16_as_ushort(lx);
}

// m16n8k16 row.col bf16 MMA with f32 accumulate (HMMA on sm_103)
__device__ __forceinline__ void mma16816(float c[4], const uint4& a, const uint2& b) {
    asm volatile(
        "mma.sync.aligned.m16n8k16.row.col.f32.bf16.bf16.f32 "
        "{%0,%1,%2,%3},{%4,%5,%6,%7},{%8,%9},{%0,%1,%2,%3};"
        : "+f"(c[0]), "+f"(c[1]), "+f"(c[2]), "+f"(c[3])
        : "r"(a.x), "r"(a.y), "r"(a.z), "r"(a.w), "r"(b.x), "r"(b.y));
}

// ---------------------------------------------------------------------------
// prep: L2-normalize prototypes; emit uint4-pair frag-packed bf16 hi/lo.
// ---------------------------------------------------------------------------
__global__ void prep_kernel(const float* __restrict__ p) {
    int k = blockIdx.x, t = threadIdx.x;       // 256 blocks x 128 threads
    float s = 0.f;
    for (int d = t; d < 512; d += 128) { float v = p[k * 512 + d]; s += v * v; }
    #pragma unroll
    for (int o = 16; o; o >>= 1) s += __shfl_xor_sync(~0u, s, o);
    __shared__ float red[4];
    if ((t & 31) == 0) red[t >> 5] = s;
    __syncthreads();
    float inv = 1.0f / fmaxf(sqrtf(red[0] + red[1] + red[2] + red[3]), 1e-12f);
    for (int d = t; d < 512; d += 128) {
        float v = p[k * 512 + d] * inv;
        __nv_bfloat16 h = __float2bfloat16(v);
        __nv_bfloat16 l = __float2bfloat16(v - __bfloat162float(h));
        unsigned short hu = __bfloat16_as_ushort(h);
        unsigned short lu = __bfloat16_as_ushort(l);
        {   // gB1: n-dim = k (proto idx), k-dim = d
            int c = d >> 5, sI = (d >> 4) & 1;
            int tp = k >> 4, hb = (k >> 3) & 1;
            int ln = (k & 7) * 4 + ((d >> 1) & 3), r = (d >> 3) & 1;
            size_t off = (((size_t)(((c * 2 + sI) * 16 + tp) * 32 + ln) * 4
                           + hb * 2 + r)) * 4 + (d & 1) * 2;
            *(unsigned short*)(g_b1h + off) = hu;
            *(unsigned short*)(g_b1l + off) = lu;
        }
        {   // gB2: n-dim = d (within half), k-dim = k
            int hf = d >> 8, c2 = k >> 5, s2 = (k >> 4) & 1;
            int tp2 = (d & 255) >> 4, hb2 = (d >> 3) & 1;
            int ln2 = (d & 7) * 4 + ((k >> 1) & 3), r2 = (k >> 3) & 1;
            size_t off = (((size_t)((((hf * 8 + c2) * 2 + s2) * 16 + tp2) * 32 + ln2) * 4
                           + hb2 * 2 + r2)) * 4 + (k & 1) * 2;
            *(unsigned short*)(g_b2h + off) = hu;
            *(unsigned short*)(g_b2l + off) = lu;
        }
    }
}

// ---------------------------------------------------------------------------
// Fused kernel: 64 rows/CTA, 256 threads (8 warps = 2 m x 4 n), 2 CTAs/SM.
// BOTH GEMM main loops are barrier-free: A/W operands from gmem-L2 / smem,
// B fragments direct LDG.128 from the L2-hot packed tables. The only
// barriers in the kernel are around sparsemax and the wf fragment exchange.
// Dynamic smem 65536 B: wfh @0 (32K) | wfl @32768 (32K)  (GEMM2 A operand)
// ---------------------------------------------------------------------------
__global__ __launch_bounds__(256, 2)
void fused_kernel(const float* __restrict__ z, float* __restrict__ out, int N) {
    extern __shared__ char smdyn[];
    __shared__ float snorm[64];
    __shared__ float ps[4][64], pc[4][64];
    __shared__ float tau_s[64], cnt_s[64];
    __shared__ int sflag;

    const int tid = threadIdx.x, lane = tid & 31, wid = tid >> 5;
    const int mw = wid >> 2, nw = wid & 3;
    const size_t row0 = (size_t)blockIdx.x * 64;
    const size_t woff = (size_t)N * 512, roff = (size_t)N * 768;

    // ---- per-row 1/||z||: 8 warps x 8 rows, float4 loads, 2-row ILP --------
    // (also makes the CTA's z rows L2-resident for the GEMM1 A loads)
    #pragma unroll 1
    for (int i = 0; i < 8; i += 2) {
        int r0_ = wid * 8 + i;
        const float4* zq0 = (const float4*)(z + (row0 + r0_) * 512) + lane;
        const float4* zq1 = (const float4*)(z + (row0 + r0_ + 1) * 512) + lane;
        float4 a0 = zq0[0], a1 = zq0[32], a2 = zq0[64], a3 = zq0[96];
        float4 b0 = zq1[0], b1 = zq1[32], b2 = zq1[64], b3 = zq1[96];
        float s0 = a0.x * a0.x + a0.y * a0.y + a0.z * a0.z + a0.w * a0.w
                 + a1.x * a1.x + a1.y * a1.y + a1.z * a1.z + a1.w * a1.w
                 + a2.x * a2.x + a2.y * a2.y + a2.z * a2.z + a2.w * a2.w
                 + a3.x * a3.x + a3.y * a3.y + a3.z * a3.z + a3.w * a3.w;
        float s1 = b0.x * b0.x + b0.y * b0.y + b0.z * b0.z + b0.w * b0.w
                 + b1.x * b1.x + b1.y * b1.y + b1.z * b1.z + b1.w * b1.w
                 + b2.x * b2.x + b2.y * b2.y + b2.z * b2.z + b2.w * b2.w
                 + b3.x * b3.x + b3.y * b3.y + b3.z * b3.z + b3.w * b3.w;
        #pragma unroll
        for (int o = 16; o; o >>= 1) {
            s0 += __shfl_xor_sync(~0u, s0, o);
            s1 += __shfl_xor_sync(~0u, s1, o);
        }
        if (lane == 0) {
            snorm[r0_] = 1.0f / fmaxf(sqrtf(s0), 1e-12f);
            snorm[r0_ + 1] = 1.0f / fmaxf(sqrtf(s1), 1e-12f);
        }
    }
    if (tid < 64) { tau_s[tid] = -3.4e38f; cnt_s[tid] = -1.f; }
    if (tid == 0) sflag = 0;
    __syncthreads();

    // ---- A fragment pointers (direct gmem) + per-row scales -----------------
    const int ar = lane >> 2, aq = (lane & 3) * 2;
    const float* zp[4];
    float sc[4];
    #pragma unroll
    for (int j = 0; j < 4; ++j) {
        int rl = mw * 32 + j * 8 + ar;
        zp[j] = z + (row0 + rl) * 512 + aq;
        sc[j] = snorm[rl] * TEMP;
    }

    float acc[2][8][4];
    #pragma unroll
    for (int mi = 0; mi < 2; ++mi)
        #pragma unroll
        for (int ni = 0; ni < 8; ++ni)
            #pragma unroll
            for (int q = 0; q < 4; ++q) acc[mi][ni][q] = 0.f;

    // ---- GEMM1: logits = (10 * z_norm) @ p_norm^T -- barrier-free ----------
    #pragma unroll 1
    for (int c = 0; c < 16; ++c) {
        // A loads for this chunk (L2/L1-hot after norm pass)
        float2 v[4][4];
        #pragma unroll
        for (int j = 0; j < 4; ++j)
            #pragma unroll
            for (int t = 0; t < 4; ++t)
                v[j][t] = *(const float2*)(zp[j] + c * 32 + t * 8);
        #pragma unroll
        for (int s = 0; s < 2; ++s) {
            // B fragments direct from L2-hot table
            size_t bbase = (((size_t)(c * 2 + s) * 16 + nw * 4) * 32 + lane) * 16;
            uint4 uh[4], ul[4];
            #pragma unroll
            for (int np = 0; np < 4; ++np) {
                uh[np] = *(const uint4*)(g_b1h + bbase + (size_t)np * 512);
                ul[np] = *(const uint4*)(g_b1l + bbase + (size_t)np * 512);
            }
            uint4 ah[2], al[2];
            #pragma unroll
            for (int mi = 0; mi < 2; ++mi) {
                uint32_t h0, l0, h1, l1, h2, l2, h3, l3;
                split2(v[2 * mi][2 * s].x * sc[2 * mi],     v[2 * mi][2 * s].y * sc[2 * mi],     h0, l0);
                split2(v[2 * mi + 1][2 * s].x * sc[2 * mi + 1], v[2 * mi + 1][2 * s].y * sc[2 * mi + 1], h1, l1);
                split2(v[2 * mi][2 * s + 1].x * sc[2 * mi],     v[2 * mi][2 * s + 1].y * sc[2 * mi],     h2, l2);
                split2(v[2 * mi + 1][2 * s + 1].x * sc[2 * mi + 1], v[2 * mi + 1][2 * s + 1].y * sc[2 * mi + 1], h3, l3);
                ah[mi] = make_uint4(h0, h1, h2, h3);
                al[mi] = make_uint4(l0, l1, l2, l3);
            }
            uint2 bf[8];
            #pragma unroll
            for (int np = 0; np < 4; ++np) {
                bf[2 * np] = make_uint2(uh[np].x, uh[np].y);
                bf[2 * np + 1] = make_uint2(uh[np].z, uh[np].w);
            }
            #pragma unroll
            for (int ni = 0; ni < 8; ++ni) {
                mma16816(acc[0][ni], ah[0], bf[ni]);
                mma16816(acc[1][ni], ah[1], bf[ni]);
                mma16816(acc[0][ni], al[0], bf[ni]);
                mma16816(acc[1][ni], al[1], bf[ni]);
            }
            #pragma unroll
            for (int np = 0; np < 4; ++np) {
                bf[2 * np] = make_uint2(ul[np].x, ul[np].y);
                bf[2 * np + 1] = make_uint2(ul[np].z, ul[np].w);
            }
            #pragma unroll
            for (int ni = 0; ni < 8; ++ni) {
                mma16816(acc[0][ni], ah[0], bf[ni]);
                mma16816(acc[1][ni], ah[1], bf[ni]);
            }
        }
    }

    // ---- sparsemax: exact Michelot fixed point, race-free uniform exit -----
    #pragma unroll 1
    for (int it = 0; it < 256; ++it) {
        #pragma unroll
        for (int mi = 0; mi < 2; ++mi) {
            #pragma unroll
            for (int h = 0; h < 2; ++h) {
                int rl = mw * 32 + mi * 16 + h * 8 + (lane >> 2);
                float tv = tau_s[rl];
                float s = 0.f, cn = 0.f;
                #pragma unroll
                for (int ni = 0; ni < 8; ++ni) {
                    float x0 = acc[mi][ni][2 * h], x1 = acc[mi][ni][2 * h + 1];
                    if (x0 > tv) { s += x0; cn += 1.f; }
                    if (x1 > tv) { s += x1; cn += 1.f; }
                }
                s += __shfl_xor_sync(~0u, s, 1); cn += __shfl_xor_sync(~0u, cn, 1);
                s += __shfl_xor_sync(~0u, s, 2); cn += __shfl_xor_sync(~0u, cn, 2);
                if ((lane & 3) == 0) { ps[nw][rl] = s; pc[nw][rl] = cn; }
            }
        }
        __syncthreads();                                   // B1
        if (tid < 64) {
            float tns = ps[0][tid] + ps[1][tid] + ps[2][tid] + ps[3][tid];
            float tnc = pc[0][tid] + pc[1][tid] + pc[2][tid] + pc[3][tid];
            if (tnc > 0.f && tnc != cnt_s[tid]) {
                cnt_s[tid] = tnc;
                tau_s[tid] = (tns - 1.0f) / tnc;
                sflag = 1;
            }
        }
        __syncthreads();                                   // B2
        int cont = sflag;
        __syncthreads();                                   // B3
        if (tid == 0) sflag = 0;
        if (!cont) break;
    }

    // ---- weights: w = max(logit - tau, 0); f32 out + fragment exchange ------
    #pragma unroll
    for (int mi = 0; mi < 2; ++mi)
        #pragma unroll
        for (int h = 0; h < 2; ++h) {
            int rl = mw * 32 + mi * 16 + h * 8 + (lane >> 2);
            float tv = tau_s[rl];
            size_t row = row0 + rl;
            #pragma unroll
            for (int ni = 0; ni < 8; ++ni) {
                float w0 = fmaxf(acc[mi][ni][2 * h] - tv, 0.f);
                float w1 = fmaxf(acc[mi][ni][2 * h + 1] - tv, 0.f);
                acc[mi][ni][2 * h] = w0;
                acc[mi][ni][2 * h + 1] = w1;
                __stcs((float2*)(out + woff + row * 256 + nw * 64 + ni * 8 + (lane & 3) * 2),
                       make_float2(w0, w1));
            }
        }
    char* wfh = smdyn;
    char* wfl = smdyn + 32768;
    #pragma unroll
    for (int mi = 0; mi < 2; ++mi) {
        #pragma unroll
        for (int sl = 0; sl < 4; ++sl) {
            int sg = nw * 4 + sl, nie = sl * 2, nio = sl * 2 + 1;
            uint32_t a0h, a0l, a1h, a1l, a2h, a2l, a3h, a3l;
            split2(acc[mi][nie][0], acc[mi][nie][1], a0h, a0l);
            split2(acc[mi][nie][2], acc[mi][nie][3], a1h, a1l);
            split2(acc[mi][nio][0], acc[mi][nio][1], a2h, a2l);
            split2(acc[mi][nio][2], acc[mi][nio][3], a3h, a3l);
            size_t off = ((size_t)(((mw * 2 + mi) * 16 + sg) * 32 + lane)) * 16;
            *(uint4*)(wfh + off) = make_uint4(a0h, a1h, a2h, a3h);
            *(uint4*)(wfl + off) = make_uint4(a0l, a1l, a2l, a3l);
        }
    }
    __syncthreads();   // wf frags visible to all warps; last barrier in kernel

    // ---- GEMM2: recon = W @ p_norm -- fully barrier-free main loop ---------
    #pragma unroll 1
    for (int hf = 0; hf < 2; ++hf) {
        float a2c[2][8][4];
        #pragma unroll
        for (int mi = 0; mi < 2; ++mi)
            #pragma unroll
            for (int ni = 0; ni < 8; ++ni)
                #pragma unroll
                for (int q = 0; q < 4; ++q) a2c[mi][ni][q] = 0.f;

        #pragma unroll 2
        for (int st = 0; st < 16; ++st) {
            size_t bbase = (((size_t)(hf * 16 + st) * 16 + nw * 4) * 32 + lane) * 16;
            uint4 uh[4], ul[4];
            #pragma unroll
            for (int np = 0; np < 4; ++np) {
                uh[np] = *(const uint4*)(g_b2h + bbase + (size_t)np * 512);
                ul[np] = *(const uint4*)(g_b2l + bbase + (size_t)np * 512);
            }
            uint4 ah[2], al[2];
            #pragma unroll
            for (int mi = 0; mi < 2; ++mi) {
                size_t off = ((size_t)(((mw * 2 + mi) * 16 + st) * 32 + lane)) * 16;
                ah[mi] = *(const uint4*)(wfh + off);
                al[mi] = *(const uint4*)(wfl + off);
            }
            uint2 bf[8];
            #pragma unroll
            for (int np = 0; np < 4; ++np) {
                bf[2 * np] = make_uint2(uh[np].x, uh[np].y);
                bf[2 * np + 1] = make_uint2(uh[np].z, uh[np].w);
            }
            #pragma unroll
            for (int ni = 0; ni < 8; ++ni) {
                mma16816(a2c[0][ni], ah[0], bf[ni]);
                mma16816(a2c[1][ni], ah[1], bf[ni]);
                mma16816(a2c[0][ni], al[0], bf[ni]);
                mma16816(a2c[1][ni], al[1], bf[ni]);
            }
            #pragma unroll
            for (int np = 0; np < 4; ++np) {
                bf[2 * np] = make_uint2(ul[np].x, ul[np].y);
                bf[2 * np + 1] = make_uint2(ul[np].z, ul[np].w);
            }
            #pragma unroll
            for (int ni = 0; ni < 8; ++ni) {
                mma16816(a2c[0][ni], ah[0], bf[ni]);
                mma16816(a2c[1][ni], ah[1], bf[ni]);
            }
        }

        // epilogue: recon + residual (registers + global only)
        #pragma unroll
        for (int mi = 0; mi < 2; ++mi)
            #pragma unroll
            for (int h = 0; h < 2; ++h) {
                int rl = mw * 32 + mi * 16 + h * 8 + (lane >> 2);
                size_t row = row0 + rl;
                float inv = snorm[rl];
                #pragma unroll
                for (int ni = 0; ni < 8; ++ni) {
                    int d = hf * 256 + nw * 64 + ni * 8 + (lane & 3) * 2;
                    float r0v = a2c[mi][ni][2 * h], r1v = a2c[mi][ni][2 * h + 1];
                    float2 zz = *(const float2*)(z + row * 512 + d);
                    __stcs((float2*)(out + row * 512 + d), make_float2(r0v, r1v));
                    __stcs((float2*)(out + roff + row * 512 + d),
                           make_float2(zz.x * inv - r0v, zz.y * inv - r1v));
                }
            }
    }
}

// ---------------------------------------------------------------------------
extern "C" void kernel_launch(void* const* d_in, const int* in_sizes, int n_in,
                              void* d_out, int out_size) {
    const float* z = (const float*)d_in[0];   // [N, 512]
    const float* p = (const float*)d_in[1];   // [256, 512]
    float* out = (float*)d_out;
    int N = in_sizes[0] / 512;

    const int smem = 65536;
    cudaFuncSetAttribute(fused_kernel,
                         cudaFuncAttributeMaxDynamicSharedMemorySize, smem);

    prep_kernel<<<256, 128>>>(p);
    fused_kernel<<<N / 64, 256, smem>>>(z, out, N);
}

// round 14
// speedup vs baseline: 1.0528x; 1.0528x over previous
#include <cuda_runtime.h>
#include <cuda_bf16.h>
#include <cstdint>
#include <math.h>

// N = 131072 (rows), D = 512, K = 256 -- fixed by dataset
#define TEMP 10.0f

// ---------------------------------------------------------------------------
// Fragment-packed prototype operands, uint4-pair order (two n-tiles per 16B):
// gB1: [c 16][s 2][tp 16][lane 32] uint4   (t = 2*tp + half; r in low/high)
// gB2: [half 2][c 8][s 2][tp 16][lane 32] uint4
// 256 KB per split each; L2-resident for the whole kernel.
// ---------------------------------------------------------------------------
__device__ __align__(16) unsigned char g_b1h[262144];
__device__ __align__(16) unsigned char g_b1l[262144];
__device__ __align__(16) unsigned char g_b2h[262144];
__device__ __align__(16) unsigned char g_b2l[262144];

__device__ __forceinline__ void split2(float x, float y, uint32_t& hi, uint32_t& lo) {
    __nv_bfloat16 hx = __float2bfloat16(x), hy = __float2bfloat16(y);
    float rx = x - __bfloat162float(hx);
    float ry = y - __bfloat162float(hy);
    __nv_bfloat16 lx = __float2bfloat16(rx), ly = __float2bfloat16(ry);
    hi = ((uint32_t)__bfloat16_as_ushort(hy) << 16) | __bfloat16_as_ushort(hx);
    lo = ((uint32_t)__bfloat16_as_ushort(ly) << 16) | __bfloat16_as_ushort(lx);
}

// m16n8k16 row.col bf16 MMA with f32 accumulate (HMMA on sm_103)
__device__ __forceinline__ void mma16816(float c[4], const uint4& a, const uint2& b) {
    asm volatile(
        "mma.sync.aligned.m16n8k16.row.col.f32.bf16.bf16.f32 "
        "{%0,%1,%2,%3},{%4,%5,%6,%7},{%8,%9},{%0,%1,%2,%3};"
        : "+f"(c[0]), "+f"(c[1]), "+f"(c[2]), "+f"(c[3])
        : "r"(a.x), "r"(a.y), "r"(a.z), "r"(a.w), "r"(b.x), "r"(b.y));
}

__device__ __forceinline__ uint32_t smem_u32(const void* p) {
    uint32_t a;
    asm("{ .reg .u64 t; cvta.to.shared.u64 t, %1; cvt.u32.u64 %0, t; }"
        : "=r"(a) : "l"(p));
    return a;
}
__device__ __forceinline__ void cpasync16(uint32_t dst, const void* src) {
    asm volatile("cp.async.cg.shared.global [%0], [%1], 16;"
                 :: "r"(dst), "l"(src));
}
#define CP_COMMIT() asm volatile("cp.async.commit_group;" ::: "memory")
#define CP_WAIT0()  asm volatile("cp.async.wait_group 0;" ::: "memory")

// ---------------------------------------------------------------------------
// prep: L2-normalize prototypes; emit uint4-pair frag-packed bf16 hi/lo.
// ---------------------------------------------------------------------------
__global__ void prep_kernel(const float* __restrict__ p) {
    int k = blockIdx.x, t = threadIdx.x;       // 256 blocks x 128 threads
    float s = 0.f;
    for (int d = t; d < 512; d += 128) { float v = p[k * 512 + d]; s += v * v; }
    #pragma unroll
    for (int o = 16; o; o >>= 1) s += __shfl_xor_sync(~0u, s, o);
    __shared__ float red[4];
    if ((t & 31) == 0) red[t >> 5] = s;
    __syncthreads();
    float inv = 1.0f / fmaxf(sqrtf(red[0] + red[1] + red[2] + red[3]), 1e-12f);
    for (int d = t; d < 512; d += 128) {
        float v = p[k * 512 + d] * inv;
        __nv_bfloat16 h = __float2bfloat16(v);
        __nv_bfloat16 l = __float2bfloat16(v - __bfloat162float(h));
        unsigned short hu = __bfloat16_as_ushort(h);
        unsigned short lu = __bfloat16_as_ushort(l);
        {   // gB1: n-dim = k (proto idx), k-dim = d
            int c = d >> 5, sI = (d >> 4) & 1;
            int tp = k >> 4, hb = (k >> 3) & 1;
            int ln = (k & 7) * 4 + ((d >> 1) & 3), r = (d >> 3) & 1;
            size_t off = (((size_t)(((c * 2 + sI) * 16 + tp) * 32 + ln) * 4
                           + hb * 2 + r)) * 4 + (d & 1) * 2;
            *(unsigned short*)(g_b1h + off) = hu;
            *(unsigned short*)(g_b1l + off) = lu;
        }
        {   // gB2: n-dim = d (within half), k-dim = k
            int hf = d >> 8, c2 = k >> 5, s2 = (k >> 4) & 1;
            int tp2 = (d & 255) >> 4, hb2 = (d >> 3) & 1;
            int ln2 = (d & 7) * 4 + ((k >> 1) & 3), r2 = (k >> 3) & 1;
            size_t off = (((size_t)((((hf * 8 + c2) * 2 + s2) * 16 + tp2) * 32 + ln2) * 4
                           + hb2 * 2 + r2)) * 4 + (k & 1) * 2;
            *(unsigned short*)(g_b2h + off) = hu;
            *(unsigned short*)(g_b2l + off) = lu;
        }
    }
}

// ---------------------------------------------------------------------------
// Fused kernel: 64 rows/CTA, 256 threads (8 warps = 2 m x 4 n), 2 CTAs/SM.
// GEMM1: A direct-gmem, B cp.async double-buffered (R12-proven).
// GEMM2: wf frags from smem, B frags direct LDG from L2-hot g_b2 tables.
// Sparsemax: register-tau, 2 barriers/iter via __syncthreads_or.
// Dynamic smem 65536 B:
//   GEMM1: buffer b @ b*32768: Bh 16K | Bl 16K
//   GEMM2: wfh @0 (32K) | wfl @32768 (32K)
// ---------------------------------------------------------------------------
__global__ __launch_bounds__(256, 2)
void fused_kernel(const float* __restrict__ z, float* __restrict__ out, int N) {
    extern __shared__ char smdyn[];
    __shared__ float snorm[64];
    __shared__ float ps[4][64], pc[4][64];

    const int tid = threadIdx.x, lane = tid & 31, wid = tid >> 5;
    const int mw = wid >> 2, nw = wid & 3;
    const size_t row0 = (size_t)blockIdx.x * 64;
    const size_t woff = (size_t)N * 512, roff = (size_t)N * 768;
    const uint32_t smbase = smem_u32(smdyn);

    // ---- GEMM1 B chunk0 prefetch FIRST (hides under norm pass) -------------
    {
        #pragma unroll
        for (int j = 0; j < 4; ++j) {
            cpasync16(smbase + (tid + j * 256) * 16, g_b1h + (tid + j * 256) * 16);
            cpasync16(smbase + 16384 + (tid + j * 256) * 16, g_b1l + (tid + j * 256) * 16);
        }
        CP_COMMIT();
    }

    // ---- per-row 1/||z||: 8 warps x 8 rows, float4 loads, 2-row ILP --------
    #pragma unroll 1
    for (int i = 0; i < 8; i += 2) {
        int r0_ = wid * 8 + i;
        const float4* zq0 = (const float4*)(z + (row0 + r0_) * 512) + lane;
        const float4* zq1 = (const float4*)(z + (row0 + r0_ + 1) * 512) + lane;
        float4 a0 = zq0[0], a1 = zq0[32], a2 = zq0[64], a3 = zq0[96];
        float4 b0 = zq1[0], b1 = zq1[32], b2 = zq1[64], b3 = zq1[96];
        float s0 = a0.x * a0.x + a0.y * a0.y + a0.z * a0.z + a0.w * a0.w
                 + a1.x * a1.x + a1.y * a1.y + a1.z * a1.z + a1.w * a1.w
                 + a2.x * a2.x + a2.y * a2.y + a2.z * a2.z + a2.w * a2.w
                 + a3.x * a3.x + a3.y * a3.y + a3.z * a3.z + a3.w * a3.w;
        float s1 = b0.x * b0.x + b0.y * b0.y + b0.z * b0.z + b0.w * b0.w
                 + b1.x * b1.x + b1.y * b1.y + b1.z * b1.z + b1.w * b1.w
                 + b2.x * b2.x + b2.y * b2.y + b2.z * b2.z + b2.w * b2.w
                 + b3.x * b3.x + b3.y * b3.y + b3.z * b3.z + b3.w * b3.w;
        #pragma unroll
        for (int o = 16; o; o >>= 1) {
            s0 += __shfl_xor_sync(~0u, s0, o);
            s1 += __shfl_xor_sync(~0u, s1, o);
        }
        if (lane == 0) {
            snorm[r0_] = 1.0f / fmaxf(sqrtf(s0), 1e-12f);
            snorm[r0_ + 1] = 1.0f / fmaxf(sqrtf(s1), 1e-12f);
        }
    }
    __syncthreads();

    // ---- A fragment pointers (direct gmem) + per-row scales -----------------
    const int ar = lane >> 2, aq = (lane & 3) * 2;
    const float* zp[4];
    float sc[4];
    #pragma unroll
    for (int j = 0; j < 4; ++j) {
        int rl = mw * 32 + j * 8 + ar;
        zp[j] = z + (row0 + rl) * 512 + aq;
        sc[j] = snorm[rl] * TEMP;
    }

    float acc[2][8][4];
    #pragma unroll
    for (int mi = 0; mi < 2; ++mi)
        #pragma unroll
        for (int ni = 0; ni < 8; ++ni)
            #pragma unroll
            for (int q = 0; q < 4; ++q) acc[mi][ni][q] = 0.f;

    // ---- GEMM1: logits = (10 * z_norm) @ p_norm^T (R12-proven pipeline) ----
    #pragma unroll 1
    for (int c = 0; c < 16; ++c) {
        CP_WAIT0();
        __syncthreads();
        const char* buf = smdyn + (size_t)(c & 1) * 32768;
        // A loads for this chunk (L2/L1-hot): 16 x LDG.64 per thread
        float2 v[4][4];
        #pragma unroll
        for (int j = 0; j < 4; ++j)
            #pragma unroll
            for (int t = 0; t < 4; ++t)
                v[j][t] = *(const float2*)(zp[j] + c * 32 + t * 8);
        // prefetch B chunk c+1
        if (c < 15) {
            int cc = c + 1;
            uint32_t bB = smbase + (uint32_t)((cc & 1) * 32768);
            #pragma unroll
            for (int j = 0; j < 4; ++j) {
                cpasync16(bB + (tid + j * 256) * 16,
                          g_b1h + (size_t)cc * 16384 + (tid + j * 256) * 16);
                cpasync16(bB + 16384 + (tid + j * 256) * 16,
                          g_b1l + (size_t)cc * 16384 + (tid + j * 256) * 16);
            }
            CP_COMMIT();
        }
        // compute chunk c
        #pragma unroll
        for (int s = 0; s < 2; ++s) {
            uint4 ah[2], al[2];
            #pragma unroll
            for (int mi = 0; mi < 2; ++mi) {
                uint32_t h0, l0, h1, l1, h2, l2, h3, l3;
                split2(v[2 * mi][2 * s].x * sc[2 * mi],     v[2 * mi][2 * s].y * sc[2 * mi],     h0, l0);
                split2(v[2 * mi + 1][2 * s].x * sc[2 * mi + 1], v[2 * mi + 1][2 * s].y * sc[2 * mi + 1], h1, l1);
                split2(v[2 * mi][2 * s + 1].x * sc[2 * mi],     v[2 * mi][2 * s + 1].y * sc[2 * mi],     h2, l2);
                split2(v[2 * mi + 1][2 * s + 1].x * sc[2 * mi + 1], v[2 * mi + 1][2 * s + 1].y * sc[2 * mi + 1], h3, l3);
                ah[mi] = make_uint4(h0, h1, h2, h3);
                al[mi] = make_uint4(l0, l1, l2, l3);
            }
            uint2 bf[8];
            #pragma unroll
            for (int np = 0; np < 4; ++np) {
                uint4 u = *(const uint4*)(buf + ((size_t)((s * 16 + nw * 4 + np) * 32 + lane)) * 16);
                bf[2 * np] = make_uint2(u.x, u.y);
                bf[2 * np + 1] = make_uint2(u.z, u.w);
            }
            #pragma unroll
            for (int ni = 0; ni < 8; ++ni) {
                mma16816(acc[0][ni], ah[0], bf[ni]);
                mma16816(acc[1][ni], ah[1], bf[ni]);
                mma16816(acc[0][ni], al[0], bf[ni]);
                mma16816(acc[1][ni], al[1], bf[ni]);
            }
            #pragma unroll
            for (int np = 0; np < 4; ++np) {
                uint4 u = *(const uint4*)(buf + 16384 + ((size_t)((s * 16 + nw * 4 + np) * 32 + lane)) * 16);
                bf[2 * np] = make_uint2(u.x, u.y);
                bf[2 * np + 1] = make_uint2(u.z, u.w);
            }
            #pragma unroll
            for (int ni = 0; ni < 8; ++ni) {
                mma16816(acc[0][ni], ah[0], bf[ni]);
                mma16816(acc[1][ni], ah[1], bf[ni]);
            }
        }
    }

    // ---- sparsemax: register-tau Michelot, 2 barriers/iter ------------------
    // Each thread owns rows rl(mi,h) = mw*32+mi*16+h*8+(lane>>2); tau/count in
    // registers, updated redundantly (deterministic: identical smem inputs and
    // op order across the 4 owning threads). Exit via __syncthreads_or.
    float tau_r[2][2], cnt_r[2][2];
    #pragma unroll
    for (int mi = 0; mi < 2; ++mi)
        #pragma unroll
        for (int h = 0; h < 2; ++h) { tau_r[mi][h] = -3.4e38f; cnt_r[mi][h] = -1.f; }

    #pragma unroll 1
    for (int it = 0; it < 256; ++it) {
        #pragma unroll
        for (int mi = 0; mi < 2; ++mi) {
            #pragma unroll
            for (int h = 0; h < 2; ++h) {
                int rl = mw * 32 + mi * 16 + h * 8 + (lane >> 2);
                float tv = tau_r[mi][h];
                float s = 0.f, cn = 0.f;
                #pragma unroll
                for (int ni = 0; ni < 8; ++ni) {
                    float x0 = acc[mi][ni][2 * h], x1 = acc[mi][ni][2 * h + 1];
                    if (x0 > tv) { s += x0; cn += 1.f; }
                    if (x1 > tv) { s += x1; cn += 1.f; }
                }
                s += __shfl_xor_sync(~0u, s, 1); cn += __shfl_xor_sync(~0u, cn, 1);
                s += __shfl_xor_sync(~0u, s, 2); cn += __shfl_xor_sync(~0u, cn, 2);
                if ((lane & 3) == 0) { ps[nw][rl] = s; pc[nw][rl] = cn; }
            }
        }
        __syncthreads();                                   // B1: partials ready
        int changed = 0;
        #pragma unroll
        for (int mi = 0; mi < 2; ++mi) {
            #pragma unroll
            for (int h = 0; h < 2; ++h) {
                int rl = mw * 32 + mi * 16 + h * 8 + (lane >> 2);
                float tns = ps[0][rl] + ps[1][rl] + ps[2][rl] + ps[3][rl];
                float tnc = pc[0][rl] + pc[1][rl] + pc[2][rl] + pc[3][rl];
                if (tnc > 0.f && tnc != cnt_r[mi][h]) {
                    cnt_r[mi][h] = tnc;
                    tau_r[mi][h] = (tns - 1.0f) / tnc;
                    changed = 1;
                }
            }
        }
        if (!__syncthreads_or(changed)) break;             // B2: uniform exit
    }

    // ---- weights: w = max(logit - tau, 0); f32 out + fragment exchange ------
    #pragma unroll
    for (int mi = 0; mi < 2; ++mi)
        #pragma unroll
        for (int h = 0; h < 2; ++h) {
            int rl = mw * 32 + mi * 16 + h * 8 + (lane >> 2);
            float tv = tau_r[mi][h];
            size_t row = row0 + rl;
            #pragma unroll
            for (int ni = 0; ni < 8; ++ni) {
                float w0 = fmaxf(acc[mi][ni][2 * h] - tv, 0.f);
                float w1 = fmaxf(acc[mi][ni][2 * h + 1] - tv, 0.f);
                acc[mi][ni][2 * h] = w0;
                acc[mi][ni][2 * h + 1] = w1;
                __stcs((float2*)(out + woff + row * 256 + nw * 64 + ni * 8 + (lane & 3) * 2),
                       make_float2(w0, w1));
            }
        }
    // GEMM1 smem dead (all reads behind sparsemax barriers); write weight frags
    char* wfh = smdyn;
    char* wfl = smdyn + 32768;
    #pragma unroll
    for (int mi = 0; mi < 2; ++mi) {
        #pragma unroll
        for (int sl = 0; sl < 4; ++sl) {
            int sg = nw * 4 + sl, nie = sl * 2, nio = sl * 2 + 1;
            uint32_t a0h, a0l, a1h, a1l, a2h, a2l, a3h, a3l;
            split2(acc[mi][nie][0], acc[mi][nie][1], a0h, a0l);
            split2(acc[mi][nie][2], acc[mi][nie][3], a1h, a1l);
            split2(acc[mi][nio][0], acc[mi][nio][1], a2h, a2l);
            split2(acc[mi][nio][2], acc[mi][nio][3], a3h, a3l);
            size_t off = ((size_t)(((mw * 2 + mi) * 16 + sg) * 32 + lane)) * 16;
            *(uint4*)(wfh + off) = make_uint4(a0h, a1h, a2h, a3h);
            *(uint4*)(wfl + off) = make_uint4(a0l, a1l, a2l, a3l);
        }
    }
    __syncthreads();   // wf frags visible to all warps; last barrier in kernel

    // ---- GEMM2: recon = W @ p_norm -- fully barrier-free main loop ---------
    #pragma unroll 1
    for (int hf = 0; hf < 2; ++hf) {
        float a2c[2][8][4];
        #pragma unroll
        for (int mi = 0; mi < 2; ++mi)
            #pragma unroll
            for (int ni = 0; ni < 8; ++ni)
                #pragma unroll
                for (int q = 0; q < 4; ++q) a2c[mi][ni][q] = 0.f;

        #pragma unroll 2
        for (int st = 0; st < 16; ++st) {
            size_t bbase = (((size_t)(hf * 16 + st) * 16 + nw * 4) * 32 + lane) * 16;
            uint4 uh[4], ul[4];
            #pragma unroll
            for (int np = 0; np < 4; ++np) {
                uh[np] = *(const uint4*)(g_b2h + bbase + (size_t)np * 512);
                ul[np] = *(const uint4*)(g_b2l + bbase + (size_t)np * 512);
            }
            uint4 ah[2], al[2];
            #pragma unroll
            for (int mi = 0; mi < 2; ++mi) {
                size_t off = ((size_t)(((mw * 2 + mi) * 16 + st) * 32 + lane)) * 16;
                ah[mi] = *(const uint4*)(wfh + off);
                al[mi] = *(const uint4*)(wfl + off);
            }
            uint2 bf[8];
            #pragma unroll
            for (int np = 0; np < 4; ++np) {
                bf[2 * np] = make_uint2(uh[np].x, uh[np].y);
                bf[2 * np + 1] = make_uint2(uh[np].z, uh[np].w);
            }
            #pragma unroll
            for (int ni = 0; ni < 8; ++ni) {
                mma16816(a2c[0][ni], ah[0], bf[ni]);
                mma16816(a2c[1][ni], ah[1], bf[ni]);
                mma16816(a2c[0][ni], al[0], bf[ni]);
                mma16816(a2c[1][ni], al[1], bf[ni]);
            }
            #pragma unroll
            for (int np = 0; np < 4; ++np) {
                bf[2 * np] = make_uint2(ul[np].x, ul[np].y);
                bf[2 * np + 1] = make_uint2(ul[np].z, ul[np].w);
            }
            #pragma unroll
            for (int ni = 0; ni < 8; ++ni) {
                mma16816(a2c[0][ni], ah[0], bf[ni]);
                mma16816(a2c[1][ni], ah[1], bf[ni]);
            }
        }

        // epilogue: recon + residual (registers + global only)
        #pragma unroll
        for (int mi = 0; mi < 2; ++mi)
            #pragma unroll
            for (int h = 0; h < 2; ++h) {
                int rl = mw * 32 + mi * 16 + h * 8 + (lane >> 2);
                size_t row = row0 + rl;
                float inv = snorm[rl];
                #pragma unroll
                for (int ni = 0; ni < 8; ++ni) {
                    int d = hf * 256 + nw * 64 + ni * 8 + (lane & 3) * 2;
                    float r0v = a2c[mi][ni][2 * h], r1v = a2c[mi][ni][2 * h + 1];
                    float2 zz = *(const float2*)(z + row * 512 + d);
                    __stcs((float2*)(out + row * 512 + d), make_float2(r0v, r1v));
                    __stcs((float2*)(out + roff + row * 512 + d),
                           make_float2(zz.x * inv - r0v, zz.y * inv - r1v));
                }
            }
    }
}

// ---------------------------------------------------------------------------
extern "C" void kernel_launch(void* const* d_in, const int* in_sizes, int n_in,
                              void* d_out, int out_size) {
    const float* z = (const float*)d_in[0];   // [N, 512]
    const float* p = (const float*)d_in[1];   // [256, 512]
    float* out = (float*)d_out;
    int N = in_sizes[0] / 512;

    const int smem = 65536;
    cudaFuncSetAttribute(fused_kernel,
                         cudaFuncAttributeMaxDynamicSharedMemorySize, smem);

    prep_kernel<<<256, 128>>>(p);
    fused_kernel<<<N / 64, 256, smem>>>(z, out, N);
}